// round 7
// baseline (speedup 1.0000x reference)
#include <cuda_runtime.h>
#include <math.h>

// FeedForwardQuantum fused v7:
//   out = cos(relu(x@W1 + b1) + theta) @ W2 + b2
// v4 structure (resident W1, ROWS=128, double-buffered x, broadcast w-LDS)
// but 512 threads/CTA and <=63 regs so 2 CTAs/SM = 32 warps (2x v4's warps,
// identical per-SM L1-wavefront and fma totals).
// GEMM1: thread=(p rows p/p+64, qh q-half, h 8d-slice of 32d chunk):
//   per chunk: 4 x-LDS + 16 w-LDS(broadcast) : 64 FFMA2, 16 indep chains.
// 4-way h-combine (2-plane tree). GEMM2: half-CTA per 64-row group, W2 in
// regs (4 cols/thread), z broadcast LDS, 2-row unroll, STG.128.

#define DDIM 1024
#define QDIM 16
#define ROWS 128
#define NTH 512
#define NCH 32
#define XSTR 36
#define PSTR 17
#define ZSTR 36

typedef unsigned long long u64;

__device__ __forceinline__ void ffma2(u64 &d, u64 a, u64 b) {
    asm("fma.rn.f32x2 %0, %1, %2, %0;" : "+l"(d) : "l"(a), "l"(b));
}
__device__ __forceinline__ float2 unpk(u64 v) {
    float2 f;
    asm("mov.b64 {%0,%1}, %2;" : "=f"(f.x), "=f"(f.y) : "l"(v));
    return f;
}
__device__ __forceinline__ u64 pk(float x, float y) {
    u64 v;
    asm("mov.b64 %0, {%1,%2};" : "=l"(v) : "f"(x), "f"(y));
    return v;
}

__global__ void __launch_bounds__(NTH, 2)
ffq_v7(const float* __restrict__ x, const float* __restrict__ W1,
       const float* __restrict__ b1, const float* __restrict__ theta,
       const float* __restrict__ W2, const float* __restrict__ b2,
       float* __restrict__ out, int nRows)
{
    extern __shared__ float sm[];
    float* w1p = sm;                       // 16384: pair-interleaved W1
    float* xb0 = w1p + DDIM * QDIM;        // 128*36 = 4608
    float* xb1 = xb0 + ROWS * XSTR;        // 4608
    float* b1s = xb1 + ROWS * XSTR;        // 16
    float* ths = b1s + QDIM;               // 16
    // post-loop aliases:
    float* pl0 = xb0;                      // 128*17 = 2176
    float* pl1 = xb0 + ROWS * PSTR;        // 2176 (4352 <= 4608)
    float* zar = xb1;                      // 128*36 (z duplicated)

    const int tid  = threadIdx.x;
    const int row0 = blockIdx.x * ROWS;

    // ---- stage W1 pair-interleaved: w1p[b*32 + 2q + pp] = W1[(2b+pp)*16+q] ----
    for (int o = tid; o < DDIM * QDIM; o += NTH) {
        int b = o >> 5, rr = o & 31, q = rr >> 1, pp = rr & 1;
        w1p[o] = W1[(2 * b + pp) * QDIM + q];
    }
    if (tid < QDIM) { b1s[tid] = b1[tid]; ths[tid] = theta[tid]; }

    // ---- GEMM1 ownership ----
    const int p  = tid & 63;               // rows p, p+64
    const int qh = (tid >> 6) & 1;         // q half (8 q)
    const int h  = tid >> 7;               // 8d-slice of chunk (0..3)

    u64 acc[16];                           // [row(2)][qj(8)]
#pragma unroll
    for (int i = 0; i < 16; i++) acc[i] = 0ULL;

    // ---- x staging: thread owns rows srow, srow+64; cols [soff, soff+4)
    const int srow = tid >> 3;             // 0..63
    const int soff = (tid & 7) * 4;
    int gr_a = row0 + srow;      if (gr_a >= nRows) gr_a = nRows - 1;
    int gr_b = row0 + srow + 64; if (gr_b >= nRows) gr_b = nRows - 1;
    const float* gpa = x + (size_t)gr_a * DDIM + soff;
    const float* gpb = x + (size_t)gr_b * DDIM + soff;

    float4 pxa = *reinterpret_cast<const float4*>(gpa);
    float4 pxb = *reinterpret_cast<const float4*>(gpb);
    *reinterpret_cast<float4*>(xb0 + srow * XSTR + soff)        = pxa;
    *reinterpret_cast<float4*>(xb0 + (srow + 64) * XSTR + soff) = pxb;
    __syncthreads();

    for (int ch = 0; ch < NCH; ch++) {
        float* cb = (ch & 1) ? xb1 : xb0;
        float* nb = (ch & 1) ? xb0 : xb1;

        if (ch + 1 < NCH) {
            int dd = (ch + 1) * 32;
            pxa = *reinterpret_cast<const float4*>(gpa + dd);
            pxb = *reinterpret_cast<const float4*>(gpb + dd);
        }

        const float* xr0 = cb + p * XSTR + 8 * h;
        const float* xr1 = xr0 + 64 * XSTR;
        ulonglong2 xa0 = *reinterpret_cast<const ulonglong2*>(xr0);
        ulonglong2 xa1 = *reinterpret_cast<const ulonglong2*>(xr0 + 4);
        ulonglong2 xq0 = *reinterpret_cast<const ulonglong2*>(xr1);
        ulonglong2 xq1 = *reinterpret_cast<const ulonglong2*>(xr1 + 4);
        u64 xp[4] = {xa0.x, xa0.y, xa1.x, xa1.y};
        u64 xq[4] = {xq0.x, xq0.y, xq1.x, xq1.y};

        const float* wb = w1p + (ch * 16 + 4 * h) * 32 + 16 * qh;
#pragma unroll
        for (int k = 0; k < 4; k++) {
            const float* wk = wb + k * 32;
            ulonglong2 wA = *reinterpret_cast<const ulonglong2*>(wk);
            ulonglong2 wB = *reinterpret_cast<const ulonglong2*>(wk + 4);
            ulonglong2 wC = *reinterpret_cast<const ulonglong2*>(wk + 8);
            ulonglong2 wD = *reinterpret_cast<const ulonglong2*>(wk + 12);
            ffma2(acc[0], xp[k], wA.x);  ffma2(acc[1], xp[k], wA.y);
            ffma2(acc[2], xp[k], wB.x);  ffma2(acc[3], xp[k], wB.y);
            ffma2(acc[4], xp[k], wC.x);  ffma2(acc[5], xp[k], wC.y);
            ffma2(acc[6], xp[k], wD.x);  ffma2(acc[7], xp[k], wD.y);
            ffma2(acc[8],  xq[k], wA.x); ffma2(acc[9],  xq[k], wA.y);
            ffma2(acc[10], xq[k], wB.x); ffma2(acc[11], xq[k], wB.y);
            ffma2(acc[12], xq[k], wC.x); ffma2(acc[13], xq[k], wC.y);
            ffma2(acc[14], xq[k], wD.x); ffma2(acc[15], xq[k], wD.y);
        }

        if (ch + 1 < NCH) {
            *reinterpret_cast<float4*>(nb + srow * XSTR + soff)        = pxa;
            *reinterpret_cast<float4*>(nb + (srow + 64) * XSTR + soff) = pxb;
        }
        __syncthreads();
    }

    // ---- 4-way h combine (2-plane tree), activation, z-dup ----
    float hv[16];
#pragma unroll
    for (int i = 0; i < 16; i++) {
        float2 a = unpk(acc[i]);
        hv[i] = a.x + a.y;
    }
    if (h == 1 || h == 3) {
        float* pl = (h == 1) ? pl0 : pl1;
#pragma unroll
        for (int j = 0; j < 8; j++) {
            pl[p * PSTR + 8 * qh + j]        = hv[j];
            pl[(p + 64) * PSTR + 8 * qh + j] = hv[8 + j];
        }
    }
    __syncthreads();
    if (h == 0) {
#pragma unroll
        for (int j = 0; j < 8; j++) {
            hv[j]     += pl0[p * PSTR + 8 * qh + j];
            hv[8 + j] += pl0[(p + 64) * PSTR + 8 * qh + j];
        }
    } else if (h == 2) {
#pragma unroll
        for (int j = 0; j < 8; j++) {
            pl1[p * PSTR + 8 * qh + j]        += hv[j];
            pl1[(p + 64) * PSTR + 8 * qh + j] += hv[8 + j];
        }
    }
    __syncthreads();
    if (h == 0) {
#pragma unroll
        for (int j = 0; j < 8; j++) {
            int q = 8 * qh + j;
            float v0 = hv[j] + pl1[p * PSTR + q] + b1s[q];
            v0 = fmaxf(v0, 0.0f) + ths[q];
            float z0 = __cosf(v0);
            zar[p * ZSTR + 2 * q]     = z0;
            zar[p * ZSTR + 2 * q + 1] = z0;
            float v1 = hv[8 + j] + pl1[(p + 64) * PSTR + q] + b1s[q];
            v1 = fmaxf(v1, 0.0f) + ths[q];
            float z1 = __cosf(v1);
            zar[(p + 64) * ZSTR + 2 * q]     = z1;
            zar[(p + 64) * ZSTR + 2 * q + 1] = z1;
        }
    }
    __syncthreads();

    // ---- GEMM2: half-CTA per 64-row group, W2 in regs, 2-row unroll ----
    const int rg   = tid >> 8;              // 0/1 -> rows rg*64 .. rg*64+63
    const int ct   = tid & 255;
    const int dcol = 4 * ct;
    const int rb2  = rg * 64;

    ulonglong2 w2r[QDIM];
#pragma unroll
    for (int q = 0; q < QDIM; q++)
        w2r[q] = *reinterpret_cast<const ulonglong2*>(W2 + q * DDIM + dcol);

    float4 b2v = *reinterpret_cast<const float4*>(b2 + dcol);
    const u64 b2p0 = pk(b2v.x, b2v.y);
    const u64 b2p1 = pk(b2v.z, b2v.w);

    for (int rr = 0; rr < 64; rr += 2) {
        u64 a0 = b2p0, a1 = b2p1, c0 = b2p0, c1 = b2p1;
        const float* z0 = zar + (rb2 + rr) * ZSTR;
        const float* z1 = z0 + ZSTR;
#pragma unroll
        for (int m = 0; m < 8; m++) {
            ulonglong2 zd0 = *reinterpret_cast<const ulonglong2*>(z0 + 4 * m);
            ulonglong2 zd1 = *reinterpret_cast<const ulonglong2*>(z1 + 4 * m);
            ffma2(a0, zd0.x, w2r[2 * m].x);
            ffma2(a1, zd0.x, w2r[2 * m].y);
            ffma2(a0, zd0.y, w2r[2 * m + 1].x);
            ffma2(a1, zd0.y, w2r[2 * m + 1].y);
            ffma2(c0, zd1.x, w2r[2 * m].x);
            ffma2(c1, zd1.x, w2r[2 * m].y);
            ffma2(c0, zd1.y, w2r[2 * m + 1].x);
            ffma2(c1, zd1.y, w2r[2 * m + 1].y);
        }
        int go = row0 + rb2 + rr;
        if (go < nRows) {
            float2 lo = unpk(a0), hi = unpk(a1);
            *reinterpret_cast<float4*>(out + (size_t)go * DDIM + dcol) =
                make_float4(lo.x, lo.y, hi.x, hi.y);
        }
        if (go + 1 < nRows) {
            float2 lo = unpk(c0), hi = unpk(c1);
            *reinterpret_cast<float4*>(out + (size_t)(go + 1) * DDIM + dcol) =
                make_float4(lo.x, lo.y, hi.x, hi.y);
        }
    }
}

extern "C" void kernel_launch(void* const* d_in, const int* in_sizes, int n_in,
                              void* d_out, int out_size) {
    const float* x     = (const float*)d_in[0];
    const float* W1    = (const float*)d_in[1];
    const float* b1    = (const float*)d_in[2];
    const float* theta = (const float*)d_in[3];
    const float* W2    = (const float*)d_in[4];
    const float* b2    = (const float*)d_in[5];
    float* out = (float*)d_out;

    int nRows = in_sizes[0] / DDIM;                    // 32768
    int grid  = (nRows + ROWS - 1) / ROWS;             // 256

    size_t smem = (size_t)(DDIM * QDIM + 2 * ROWS * XSTR + 2 * QDIM) * sizeof(float);
    static int attr_set = 0;
    if (!attr_set) {
        cudaFuncSetAttribute(ffq_v7, cudaFuncAttributeMaxDynamicSharedMemorySize,
                             (int)smem);
        attr_set = 1;
    }

    ffq_v7<<<grid, NTH, smem>>>(x, W1, b1, theta, W2, b2, out, nRows);
}

// round 9
// speedup vs baseline: 2.0565x; 2.0565x over previous
#include <cuda_runtime.h>
#include <math.h>

// FeedForwardQuantum fused v9 (v8 with GEMM2 q-octet indexing fixed):
//   out = cos(relu(x@W1 + b1) + theta) @ W2 + b2
// - resident pair-interleaved W1, ROWS=128, NTH=256, 2 CTAs/SM
// - cp.async (LDGSTS) x staging, double-buffered, 1 sync/chunk
// - GEMM1: broadcast w-LDS -> fma.rn.f32x2, 16 indep acc chains
// - GEMM2: W2 in regs, 4-row unroll, grouped z-LDS, STG.128

#define DDIM 1024
#define QDIM 16
#define ROWS 128
#define NTH 256
#define NCH 32
#define XSTR 36
#define PSTR 17
#define ZSTR 36

typedef unsigned long long u64;

__device__ __forceinline__ void ffma2(u64 &d, u64 a, u64 b) {
    asm("fma.rn.f32x2 %0, %1, %2, %0;" : "+l"(d) : "l"(a), "l"(b));
}
__device__ __forceinline__ float2 unpk(u64 v) {
    float2 f;
    asm("mov.b64 {%0,%1}, %2;" : "=f"(f.x), "=f"(f.y) : "l"(v));
    return f;
}
__device__ __forceinline__ u64 pk(float x, float y) {
    u64 v;
    asm("mov.b64 %0, {%1,%2};" : "=l"(v) : "f"(x), "f"(y));
    return v;
}
__device__ __forceinline__ unsigned s2u(const void* p) {
    unsigned a;
    asm("{ .reg .u64 t; cvta.to.shared.u64 t, %1; cvt.u32.u64 %0, t; }"
        : "=r"(a) : "l"(p));
    return a;
}
#define CP16(dst, src) \
    asm volatile("cp.async.cg.shared.global [%0], [%1], 16;" :: "r"(dst), "l"(src))
#define CPCOMMIT() asm volatile("cp.async.commit_group;")
#define CPWAIT0()  asm volatile("cp.async.wait_group 0;")

__global__ void __launch_bounds__(NTH, 2)
ffq_v9(const float* __restrict__ x, const float* __restrict__ W1,
       const float* __restrict__ b1, const float* __restrict__ theta,
       const float* __restrict__ W2, const float* __restrict__ b2,
       float* __restrict__ out, int nRows)
{
    extern __shared__ float sm[];
    float* w1p = sm;                       // 16384: pair-interleaved W1
    float* xb0 = w1p + DDIM * QDIM;        // 128*36 = 4608
    float* xb1 = xb0 + ROWS * XSTR;        // 4608
    float* b1s = xb1 + ROWS * XSTR;        // 16
    float* ths = b1s + QDIM;               // 16
    // post-loop aliases:
    float* ps  = xb0;                      // 128*17 = 2176 (h partials)
    float* zar = xb1;                      // 128*36 (z duplicated)

    const int tid  = threadIdx.x;
    const int row0 = blockIdx.x * ROWS;

    // ---- stage W1 pair-interleaved: w1p[b*32 + 2q + pp] = W1[(2b+pp)*16+q] ----
    for (int o = tid; o < DDIM * QDIM; o += NTH) {
        int b = o >> 5, rr = o & 31, q = rr >> 1, pp = rr & 1;
        w1p[o] = W1[(2 * b + pp) * QDIM + q];
    }
    if (tid < QDIM) { b1s[tid] = b1[tid]; ths[tid] = theta[tid]; }

    // ---- GEMM1 ownership: rows p, p+64; q-half qh; d-half h (16d) ----
    const int p  = tid & 63;
    const int qh = (tid >> 6) & 1;
    const int h  = tid >> 7;

    u64 acc[16];                           // [row(2)][q-pair(8)]
#pragma unroll
    for (int i = 0; i < 16; i++) acc[i] = 0ULL;

    // ---- cp.async staging: thread owns 4x 16B: row rb+32k, col quad c4 ----
    const int c4 = (tid & 7) * 4;
    const int rb = tid >> 3;
    const float* gp[4];
#pragma unroll
    for (int k = 0; k < 4; k++) {
        int gr = row0 + rb + 32 * k;
        if (gr >= nRows) gr = nRows - 1;
        gp[k] = x + (size_t)gr * DDIM + c4;
    }
    const unsigned xb0a = s2u(xb0);
    const unsigned xb1a = s2u(xb1);
    const unsigned soff = (unsigned)((rb * XSTR + c4) * 4);

    // prologue: chunk 0 -> xb0
#pragma unroll
    for (int k = 0; k < 4; k++)
        CP16(xb0a + soff + (unsigned)(32 * k * XSTR * 4), gp[k]);
    CPCOMMIT();

    for (int ch = 0; ch < NCH; ch++) {
        const float* cb = (ch & 1) ? xb1 : xb0;
        const unsigned nba = (ch & 1) ? xb0a : xb1a;

        CPWAIT0();
        __syncthreads();

        if (ch + 1 < NCH) {
            int dd = (ch + 1) * 32;
#pragma unroll
            for (int k = 0; k < 4; k++)
                CP16(nba + soff + (unsigned)(32 * k * XSTR * 4), gp[k] + dd);
            CPCOMMIT();
        }

        const float* xrow = cb + p * XSTR + 16 * h;
        const float* xro1 = xrow + 64 * XSTR;
        const float* wch  = w1p + (ch * 32 + 16 * h) * QDIM + 16 * qh;
#pragma unroll
        for (int db = 0; db < 16; db += 4) {
            ulonglong2 xa = *reinterpret_cast<const ulonglong2*>(xrow + db);
            ulonglong2 xb = *reinterpret_cast<const ulonglong2*>(xro1 + db);
            const float* wq = wch + (db >> 1) * 32;     // d-pair block b0
            ulonglong2 wA0 = *reinterpret_cast<const ulonglong2*>(wq);
            ulonglong2 wA1 = *reinterpret_cast<const ulonglong2*>(wq + 4);
            ulonglong2 wA2 = *reinterpret_cast<const ulonglong2*>(wq + 8);
            ulonglong2 wA3 = *reinterpret_cast<const ulonglong2*>(wq + 12);
            ffma2(acc[0], xa.x, wA0.x);  ffma2(acc[1], xa.x, wA0.y);
            ffma2(acc[2], xa.x, wA1.x);  ffma2(acc[3], xa.x, wA1.y);
            ffma2(acc[4], xa.x, wA2.x);  ffma2(acc[5], xa.x, wA2.y);
            ffma2(acc[6], xa.x, wA3.x);  ffma2(acc[7], xa.x, wA3.y);
            ffma2(acc[8],  xb.x, wA0.x); ffma2(acc[9],  xb.x, wA0.y);
            ffma2(acc[10], xb.x, wA1.x); ffma2(acc[11], xb.x, wA1.y);
            ffma2(acc[12], xb.x, wA2.x); ffma2(acc[13], xb.x, wA2.y);
            ffma2(acc[14], xb.x, wA3.x); ffma2(acc[15], xb.x, wA3.y);
            const float* wr = wq + 32;                   // d-pair block b1
            ulonglong2 wB0 = *reinterpret_cast<const ulonglong2*>(wr);
            ulonglong2 wB1 = *reinterpret_cast<const ulonglong2*>(wr + 4);
            ulonglong2 wB2 = *reinterpret_cast<const ulonglong2*>(wr + 8);
            ulonglong2 wB3 = *reinterpret_cast<const ulonglong2*>(wr + 12);
            ffma2(acc[0], xa.y, wB0.x);  ffma2(acc[1], xa.y, wB0.y);
            ffma2(acc[2], xa.y, wB1.x);  ffma2(acc[3], xa.y, wB1.y);
            ffma2(acc[4], xa.y, wB2.x);  ffma2(acc[5], xa.y, wB2.y);
            ffma2(acc[6], xa.y, wB3.x);  ffma2(acc[7], xa.y, wB3.y);
            ffma2(acc[8],  xb.y, wB0.x); ffma2(acc[9],  xb.y, wB0.y);
            ffma2(acc[10], xb.y, wB1.x); ffma2(acc[11], xb.y, wB1.y);
            ffma2(acc[12], xb.y, wB2.x); ffma2(acc[13], xb.y, wB2.y);
            ffma2(acc[14], xb.y, wB3.x); ffma2(acc[15], xb.y, wB3.y);
        }
    }

    // ---- combine d-halves, activation, z-dup (ps=xb0 free; zar=xb1) ----
    float hv[16];
#pragma unroll
    for (int i = 0; i < 16; i++) {
        float2 a = unpk(acc[i]);
        hv[i] = a.x + a.y;
    }
    if (h == 1) {
#pragma unroll
        for (int j = 0; j < 8; j++) {
            ps[p * PSTR + 8 * qh + j]        = hv[j];
            ps[(p + 64) * PSTR + 8 * qh + j] = hv[8 + j];
        }
    }
    __syncthreads();
    if (h == 0) {
#pragma unroll
        for (int j = 0; j < 8; j++) {
            int q = 8 * qh + j;
            float v0 = hv[j] + ps[p * PSTR + q] + b1s[q];
            v0 = fmaxf(v0, 0.0f) + ths[q];
            float z0 = __cosf(v0);
            zar[p * ZSTR + 2 * q]     = z0;
            zar[p * ZSTR + 2 * q + 1] = z0;
            float v1 = hv[8 + j] + ps[(p + 64) * PSTR + q] + b1s[q];
            v1 = fmaxf(v1, 0.0f) + ths[q];
            float z1 = __cosf(v1);
            zar[(p + 64) * ZSTR + 2 * q]     = z1;
            zar[(p + 64) * ZSTR + 2 * q + 1] = z1;
        }
    }
    __syncthreads();

    // ---- GEMM2: W2 in regs, z broadcast LDS, 4-row unroll, STG.128 ----
    // z row layout: float [8m..8m+7] = (z_{4m},z_{4m},z_{4m+1},z_{4m+1},
    //                                   z_{4m+2},z_{4m+2},z_{4m+3},z_{4m+3})
    const int dcol = 4 * tid;
    ulonglong2 w2r[QDIM];
#pragma unroll
    for (int q = 0; q < QDIM; q++)
        w2r[q] = *reinterpret_cast<const ulonglong2*>(W2 + q * DDIM + dcol);

    float4 b2v = *reinterpret_cast<const float4*>(b2 + dcol);
    const u64 b2p0 = pk(b2v.x, b2v.y);
    const u64 b2p1 = pk(b2v.z, b2v.w);

    for (int rr = 0; rr < ROWS; rr += 4) {
        u64 a0 = b2p0, a1 = b2p1, c0 = b2p0, c1 = b2p1;
        u64 e0 = b2p0, e1 = b2p1, f0 = b2p0, f1 = b2p1;
        const float* z0 = zar + rr * ZSTR;
        const float* z1 = z0 + ZSTR;
        const float* z2 = z1 + ZSTR;
        const float* z3 = z2 + ZSTR;
        ulonglong2 zd0[4], zd1[4], zd2[4], zd3[4];
        // octet 1: floats 8m..8m+3  -> q = 4m, 4m+1
#pragma unroll
        for (int m = 0; m < 4; m++) {
            zd0[m] = *reinterpret_cast<const ulonglong2*>(z0 + 8 * m);
            zd1[m] = *reinterpret_cast<const ulonglong2*>(z1 + 8 * m);
            zd2[m] = *reinterpret_cast<const ulonglong2*>(z2 + 8 * m);
            zd3[m] = *reinterpret_cast<const ulonglong2*>(z3 + 8 * m);
        }
#pragma unroll
        for (int m = 0; m < 4; m++) {
            ffma2(a0, zd0[m].x, w2r[4 * m].x);     ffma2(a1, zd0[m].x, w2r[4 * m].y);
            ffma2(a0, zd0[m].y, w2r[4 * m + 1].x); ffma2(a1, zd0[m].y, w2r[4 * m + 1].y);
            ffma2(c0, zd1[m].x, w2r[4 * m].x);     ffma2(c1, zd1[m].x, w2r[4 * m].y);
            ffma2(c0, zd1[m].y, w2r[4 * m + 1].x); ffma2(c1, zd1[m].y, w2r[4 * m + 1].y);
            ffma2(e0, zd2[m].x, w2r[4 * m].x);     ffma2(e1, zd2[m].x, w2r[4 * m].y);
            ffma2(e0, zd2[m].y, w2r[4 * m + 1].x); ffma2(e1, zd2[m].y, w2r[4 * m + 1].y);
            ffma2(f0, zd3[m].x, w2r[4 * m].x);     ffma2(f1, zd3[m].x, w2r[4 * m].y);
            ffma2(f0, zd3[m].y, w2r[4 * m + 1].x); ffma2(f1, zd3[m].y, w2r[4 * m + 1].y);
        }
        // octet 2: floats 8m+4..8m+7 -> q = 4m+2, 4m+3
#pragma unroll
        for (int m = 0; m < 4; m++) {
            zd0[m] = *reinterpret_cast<const ulonglong2*>(z0 + 8 * m + 4);
            zd1[m] = *reinterpret_cast<const ulonglong2*>(z1 + 8 * m + 4);
            zd2[m] = *reinterpret_cast<const ulonglong2*>(z2 + 8 * m + 4);
            zd3[m] = *reinterpret_cast<const ulonglong2*>(z3 + 8 * m + 4);
        }
#pragma unroll
        for (int m = 0; m < 4; m++) {
            ffma2(a0, zd0[m].x, w2r[4 * m + 2].x); ffma2(a1, zd0[m].x, w2r[4 * m + 2].y);
            ffma2(a0, zd0[m].y, w2r[4 * m + 3].x); ffma2(a1, zd0[m].y, w2r[4 * m + 3].y);
            ffma2(c0, zd1[m].x, w2r[4 * m + 2].x); ffma2(c1, zd1[m].x, w2r[4 * m + 2].y);
            ffma2(c0, zd1[m].y, w2r[4 * m + 3].x); ffma2(c1, zd1[m].y, w2r[4 * m + 3].y);
            ffma2(e0, zd2[m].x, w2r[4 * m + 2].x); ffma2(e1, zd2[m].x, w2r[4 * m + 2].y);
            ffma2(e0, zd2[m].y, w2r[4 * m + 3].x); ffma2(e1, zd2[m].y, w2r[4 * m + 3].y);
            ffma2(f0, zd3[m].x, w2r[4 * m + 2].x); ffma2(f1, zd3[m].x, w2r[4 * m + 2].y);
            ffma2(f0, zd3[m].y, w2r[4 * m + 3].x); ffma2(f1, zd3[m].y, w2r[4 * m + 3].y);
        }

        int go = row0 + rr;
        float2 lo, hi;
        if (go < nRows) {
            lo = unpk(a0); hi = unpk(a1);
            *reinterpret_cast<float4*>(out + (size_t)go * DDIM + dcol) =
                make_float4(lo.x, lo.y, hi.x, hi.y);
        }
        if (go + 1 < nRows) {
            lo = unpk(c0); hi = unpk(c1);
            *reinterpret_cast<float4*>(out + (size_t)(go + 1) * DDIM + dcol) =
                make_float4(lo.x, lo.y, hi.x, hi.y);
        }
        if (go + 2 < nRows) {
            lo = unpk(e0); hi = unpk(e1);
            *reinterpret_cast<float4*>(out + (size_t)(go + 2) * DDIM + dcol) =
                make_float4(lo.x, lo.y, hi.x, hi.y);
        }
        if (go + 3 < nRows) {
            lo = unpk(f0); hi = unpk(f1);
            *reinterpret_cast<float4*>(out + (size_t)(go + 3) * DDIM + dcol) =
                make_float4(lo.x, lo.y, hi.x, hi.y);
        }
    }
}

extern "C" void kernel_launch(void* const* d_in, const int* in_sizes, int n_in,
                              void* d_out, int out_size) {
    const float* x     = (const float*)d_in[0];
    const float* W1    = (const float*)d_in[1];
    const float* b1    = (const float*)d_in[2];
    const float* theta = (const float*)d_in[3];
    const float* W2    = (const float*)d_in[4];
    const float* b2    = (const float*)d_in[5];
    float* out = (float*)d_out;

    int nRows = in_sizes[0] / DDIM;                    // 32768
    int grid  = (nRows + ROWS - 1) / ROWS;             // 256

    size_t smem = (size_t)(DDIM * QDIM + 2 * ROWS * XSTR + 2 * QDIM) * sizeof(float);
    static int attr_set = 0;
    if (!attr_set) {
        cudaFuncSetAttribute(ffq_v9, cudaFuncAttributeMaxDynamicSharedMemorySize,
                             (int)smem);
        attr_set = 1;
    }

    ffq_v9<<<grid, NTH, smem>>>(x, W1, b1, theta, W2, b2, out, nRows);
}

// round 10
// speedup vs baseline: 2.0803x; 1.0116x over previous
#include <cuda_runtime.h>
#include <math.h>

// FeedForwardQuantum fused v10:
//   out = cos(relu(x@W1 + b1) + theta) @ W2 + b2
// Key change vs v9: 8-byte XOR-swizzled x chunk layout
//   addr(row, pair e) = row*32 + 2*(e ^ (row & 15))   (stride 32 = bank-neutral)
// -> LDS.64 compute reads give (x_d,x_{d+1}) u64 operands directly, 2-way
//    conflict max (was 4-way on every access with stride 36).
// Staging: LDG.128 register prefetch + STS.64 swizzled; 1 sync/chunk.
// GEMM1: broadcast w-LDS.128 -> fma.rn.f32x2, 16 indep acc chains.
// GEMM2: W2 in regs, 4-row unroll, grouped broadcast z-LDS, STG.128.

#define DDIM 1024
#define QDIM 16
#define ROWS 128
#define NTH 256
#define NCH 32
#define PSTR 17

typedef unsigned long long u64;

__device__ __forceinline__ void ffma2(u64 &d, u64 a, u64 b) {
    asm("fma.rn.f32x2 %0, %1, %2, %0;" : "+l"(d) : "l"(a), "l"(b));
}
__device__ __forceinline__ float2 unpk(u64 v) {
    float2 f;
    asm("mov.b64 {%0,%1}, %2;" : "=f"(f.x), "=f"(f.y) : "l"(v));
    return f;
}
__device__ __forceinline__ u64 pk(float x, float y) {
    u64 v;
    asm("mov.b64 %0, {%1,%2};" : "=l"(v) : "f"(x), "f"(y));
    return v;
}

__global__ void __launch_bounds__(NTH, 2)
ffq_v10(const float* __restrict__ x, const float* __restrict__ W1,
        const float* __restrict__ b1, const float* __restrict__ theta,
        const float* __restrict__ W2, const float* __restrict__ b2,
        float* __restrict__ out, int nRows)
{
    extern __shared__ float sm[];
    float* w1p = sm;                       // 16384: pair-interleaved W1
    float* xb0 = w1p + DDIM * QDIM;        // 128*32 = 4096 (swizzled x chunk)
    float* xb1 = xb0 + ROWS * 32;          // 4096
    float* b1s = xb1 + ROWS * 32;          // 16
    float* ths = b1s + QDIM;               // 16
    // post-loop aliases:
    float* ps  = xb0;                      // 128*17 = 2176 (h partials)
    float* zar = xb1;                      // 128*32 (z duplicated, ZSTR=32)

    const int tid  = threadIdx.x;
    const int row0 = blockIdx.x * ROWS;

    // ---- stage W1 pair-interleaved: w1p[b*32 + 2q + pp] = W1[(2b+pp)*16+q] ----
    for (int o = tid; o < DDIM * QDIM; o += NTH) {
        int b = o >> 5, rr = o & 31, q = rr >> 1, pp = rr & 1;
        w1p[o] = W1[(2 * b + pp) * QDIM + q];
    }
    if (tid < QDIM) { b1s[tid] = b1[tid]; ths[tid] = theta[tid]; }

    // ---- GEMM1 ownership: rows p, p+64; q-half qh; d-half h (16d) ----
    const int p   = tid & 63;
    const int qh  = (tid >> 6) & 1;
    const int h   = tid >> 7;
    const int key = p & 15;                // swizzle key ((p+64)&15 == key)

    u64 acc[16];                           // [row(2)][q-pair(8)]
#pragma unroll
    for (int i = 0; i < 16; i++) acc[i] = 0ULL;

    // ---- staging ownership: rows rb+32k (k=0..3), float quad c4 ----
    const int c4 = (tid & 7) * 4;
    const int rb = tid >> 3;               // 0..31
    const int e0 = c4 >> 1;                // even pair index
    const int keyS = rb & 15;
    const int so0 = 2 * (e0 ^ keyS);       // swizzled float offsets
    const int so1 = 2 * ((e0 + 1) ^ keyS);
    const float* gp[4];
#pragma unroll
    for (int k = 0; k < 4; k++) {
        int gr = row0 + rb + 32 * k;
        if (gr >= nRows) gr = nRows - 1;
        gp[k] = x + (size_t)gr * DDIM + c4;
    }

    // prologue: chunk 0 -> xb0
    {
        float4 pf[4];
#pragma unroll
        for (int k = 0; k < 4; k++) pf[k] = *reinterpret_cast<const float4*>(gp[k]);
#pragma unroll
        for (int k = 0; k < 4; k++) {
            float* dst = xb0 + (rb + 32 * k) * 32;
            *reinterpret_cast<u64*>(dst + so0) = pk(pf[k].x, pf[k].y);
            *reinterpret_cast<u64*>(dst + so1) = pk(pf[k].z, pf[k].w);
        }
    }
    __syncthreads();

    for (int ch = 0; ch < NCH; ch++) {
        const float* cb = (ch & 1) ? xb1 : xb0;
        float*       nb = (ch & 1) ? xb0 : xb1;

        // prefetch next chunk into registers (LDG covered by compute below)
        float4 pf[4];
        if (ch + 1 < NCH) {
            int dd = (ch + 1) * 32;
#pragma unroll
            for (int k = 0; k < 4; k++)
                pf[k] = *reinterpret_cast<const float4*>(gp[k] + dd);
        }

        const float* r0b = cb + p * 32;
        const float* r1b = cb + (p + 64) * 32;
        const float* wch = w1p + (ch * 32 + 16 * h) * QDIM + 16 * qh;
#pragma unroll
        for (int t = 0; t < 4; t++) {
            int ea = 8 * h + 2 * t;
            u64 xalo = *reinterpret_cast<const u64*>(r0b + 2 * (ea ^ key));
            u64 xahi = *reinterpret_cast<const u64*>(r0b + 2 * ((ea + 1) ^ key));
            u64 xblo = *reinterpret_cast<const u64*>(r1b + 2 * (ea ^ key));
            u64 xbhi = *reinterpret_cast<const u64*>(r1b + 2 * ((ea + 1) ^ key));
            const float* wq = wch + t * 64;            // d-pair block b0
            ulonglong2 wA0 = *reinterpret_cast<const ulonglong2*>(wq);
            ulonglong2 wA1 = *reinterpret_cast<const ulonglong2*>(wq + 4);
            ulonglong2 wA2 = *reinterpret_cast<const ulonglong2*>(wq + 8);
            ulonglong2 wA3 = *reinterpret_cast<const ulonglong2*>(wq + 12);
            ffma2(acc[0], xalo, wA0.x);  ffma2(acc[1], xalo, wA0.y);
            ffma2(acc[2], xalo, wA1.x);  ffma2(acc[3], xalo, wA1.y);
            ffma2(acc[4], xalo, wA2.x);  ffma2(acc[5], xalo, wA2.y);
            ffma2(acc[6], xalo, wA3.x);  ffma2(acc[7], xalo, wA3.y);
            ffma2(acc[8],  xblo, wA0.x); ffma2(acc[9],  xblo, wA0.y);
            ffma2(acc[10], xblo, wA1.x); ffma2(acc[11], xblo, wA1.y);
            ffma2(acc[12], xblo, wA2.x); ffma2(acc[13], xblo, wA2.y);
            ffma2(acc[14], xblo, wA3.x); ffma2(acc[15], xblo, wA3.y);
            const float* wr = wq + 32;                 // d-pair block b1
            ulonglong2 wB0 = *reinterpret_cast<const ulonglong2*>(wr);
            ulonglong2 wB1 = *reinterpret_cast<const ulonglong2*>(wr + 4);
            ulonglong2 wB2 = *reinterpret_cast<const ulonglong2*>(wr + 8);
            ulonglong2 wB3 = *reinterpret_cast<const ulonglong2*>(wr + 12);
            ffma2(acc[0], xahi, wB0.x);  ffma2(acc[1], xahi, wB0.y);
            ffma2(acc[2], xahi, wB1.x);  ffma2(acc[3], xahi, wB1.y);
            ffma2(acc[4], xahi, wB2.x);  ffma2(acc[5], xahi, wB2.y);
            ffma2(acc[6], xahi, wB3.x);  ffma2(acc[7], xahi, wB3.y);
            ffma2(acc[8],  xbhi, wB0.x); ffma2(acc[9],  xbhi, wB0.y);
            ffma2(acc[10], xbhi, wB1.x); ffma2(acc[11], xbhi, wB1.y);
            ffma2(acc[12], xbhi, wB2.x); ffma2(acc[13], xbhi, wB2.y);
            ffma2(acc[14], xbhi, wB3.x); ffma2(acc[15], xbhi, wB3.y);
        }

        if (ch + 1 < NCH) {
#pragma unroll
            for (int k = 0; k < 4; k++) {
                float* dst = nb + (rb + 32 * k) * 32;
                *reinterpret_cast<u64*>(dst + so0) = pk(pf[k].x, pf[k].y);
                *reinterpret_cast<u64*>(dst + so1) = pk(pf[k].z, pf[k].w);
            }
        }
        __syncthreads();
    }

    // ---- combine d-halves, activation, z-dup (ps=xb0; zar=xb1) ----
    float hv[16];
#pragma unroll
    for (int i = 0; i < 16; i++) {
        float2 a = unpk(acc[i]);
        hv[i] = a.x + a.y;
    }
    if (h == 1) {
#pragma unroll
        for (int j = 0; j < 8; j++) {
            ps[p * PSTR + 8 * qh + j]        = hv[j];
            ps[(p + 64) * PSTR + 8 * qh + j] = hv[8 + j];
        }
    }
    __syncthreads();
    if (h == 0) {
#pragma unroll
        for (int j = 0; j < 8; j++) {
            int q = 8 * qh + j;
            float v0 = hv[j] + ps[p * PSTR + q] + b1s[q];
            v0 = fmaxf(v0, 0.0f) + ths[q];
            float z0 = __cosf(v0);
            zar[p * 32 + 2 * q]     = z0;
            zar[p * 32 + 2 * q + 1] = z0;
            float v1 = hv[8 + j] + ps[(p + 64) * PSTR + q] + b1s[q];
            v1 = fmaxf(v1, 0.0f) + ths[q];
            float z1 = __cosf(v1);
            zar[(p + 64) * 32 + 2 * q]     = z1;
            zar[(p + 64) * 32 + 2 * q + 1] = z1;
        }
    }
    __syncthreads();

    // ---- GEMM2: W2 in regs, broadcast z-LDS, 4-row unroll, STG.128 ----
    // z row layout: float [8m..8m+7] = (z_{4m},z_{4m},z_{4m+1},z_{4m+1},
    //                                   z_{4m+2},z_{4m+2},z_{4m+3},z_{4m+3})
    const int dcol = 4 * tid;
    ulonglong2 w2r[QDIM];
#pragma unroll
    for (int q = 0; q < QDIM; q++)
        w2r[q] = *reinterpret_cast<const ulonglong2*>(W2 + q * DDIM + dcol);

    float4 b2v = *reinterpret_cast<const float4*>(b2 + dcol);
    const u64 b2p0 = pk(b2v.x, b2v.y);
    const u64 b2p1 = pk(b2v.z, b2v.w);

    for (int rr = 0; rr < ROWS; rr += 4) {
        u64 a0 = b2p0, a1 = b2p1, c0 = b2p0, c1 = b2p1;
        u64 e0a = b2p0, e1a = b2p1, f0 = b2p0, f1 = b2p1;
        const float* z0 = zar + rr * 32;
        const float* z1 = z0 + 32;
        const float* z2 = z1 + 32;
        const float* z3 = z2 + 32;
        ulonglong2 zd0[4], zd1[4], zd2[4], zd3[4];
        // octet 1: floats 8m..8m+3  -> q = 4m, 4m+1
#pragma unroll
        for (int m = 0; m < 4; m++) {
            zd0[m] = *reinterpret_cast<const ulonglong2*>(z0 + 8 * m);
            zd1[m] = *reinterpret_cast<const ulonglong2*>(z1 + 8 * m);
            zd2[m] = *reinterpret_cast<const ulonglong2*>(z2 + 8 * m);
            zd3[m] = *reinterpret_cast<const ulonglong2*>(z3 + 8 * m);
        }
#pragma unroll
        for (int m = 0; m < 4; m++) {
            ffma2(a0, zd0[m].x, w2r[4 * m].x);      ffma2(a1, zd0[m].x, w2r[4 * m].y);
            ffma2(a0, zd0[m].y, w2r[4 * m + 1].x);  ffma2(a1, zd0[m].y, w2r[4 * m + 1].y);
            ffma2(c0, zd1[m].x, w2r[4 * m].x);      ffma2(c1, zd1[m].x, w2r[4 * m].y);
            ffma2(c0, zd1[m].y, w2r[4 * m + 1].x);  ffma2(c1, zd1[m].y, w2r[4 * m + 1].y);
            ffma2(e0a, zd2[m].x, w2r[4 * m].x);     ffma2(e1a, zd2[m].x, w2r[4 * m].y);
            ffma2(e0a, zd2[m].y, w2r[4 * m + 1].x); ffma2(e1a, zd2[m].y, w2r[4 * m + 1].y);
            ffma2(f0, zd3[m].x, w2r[4 * m].x);      ffma2(f1, zd3[m].x, w2r[4 * m].y);
            ffma2(f0, zd3[m].y, w2r[4 * m + 1].x);  ffma2(f1, zd3[m].y, w2r[4 * m + 1].y);
        }
        // octet 2: floats 8m+4..8m+7 -> q = 4m+2, 4m+3
#pragma unroll
        for (int m = 0; m < 4; m++) {
            zd0[m] = *reinterpret_cast<const ulonglong2*>(z0 + 8 * m + 4);
            zd1[m] = *reinterpret_cast<const ulonglong2*>(z1 + 8 * m + 4);
            zd2[m] = *reinterpret_cast<const ulonglong2*>(z2 + 8 * m + 4);
            zd3[m] = *reinterpret_cast<const ulonglong2*>(z3 + 8 * m + 4);
        }
#pragma unroll
        for (int m = 0; m < 4; m++) {
            ffma2(a0, zd0[m].x, w2r[4 * m + 2].x);  ffma2(a1, zd0[m].x, w2r[4 * m + 2].y);
            ffma2(a0, zd0[m].y, w2r[4 * m + 3].x);  ffma2(a1, zd0[m].y, w2r[4 * m + 3].y);
            ffma2(c0, zd1[m].x, w2r[4 * m + 2].x);  ffma2(c1, zd1[m].x, w2r[4 * m + 2].y);
            ffma2(c0, zd1[m].y, w2r[4 * m + 3].x);  ffma2(c1, zd1[m].y, w2r[4 * m + 3].y);
            ffma2(e0a, zd2[m].x, w2r[4 * m + 2].x); ffma2(e1a, zd2[m].x, w2r[4 * m + 2].y);
            ffma2(e0a, zd2[m].y, w2r[4 * m + 3].x); ffma2(e1a, zd2[m].y, w2r[4 * m + 3].y);
            ffma2(f0, zd3[m].x, w2r[4 * m + 2].x);  ffma2(f1, zd3[m].x, w2r[4 * m + 2].y);
            ffma2(f0, zd3[m].y, w2r[4 * m + 3].x);  ffma2(f1, zd3[m].y, w2r[4 * m + 3].y);
        }

        int go = row0 + rr;
        float2 lo, hi;
        if (go < nRows) {
            lo = unpk(a0); hi = unpk(a1);
            *reinterpret_cast<float4*>(out + (size_t)go * DDIM + dcol) =
                make_float4(lo.x, lo.y, hi.x, hi.y);
        }
        if (go + 1 < nRows) {
            lo = unpk(c0); hi = unpk(c1);
            *reinterpret_cast<float4*>(out + (size_t)(go + 1) * DDIM + dcol) =
                make_float4(lo.x, lo.y, hi.x, hi.y);
        }
        if (go + 2 < nRows) {
            lo = unpk(e0a); hi = unpk(e1a);
            *reinterpret_cast<float4*>(out + (size_t)(go + 2) * DDIM + dcol) =
                make_float4(lo.x, lo.y, hi.x, hi.y);
        }
        if (go + 3 < nRows) {
            lo = unpk(f0); hi = unpk(f1);
            *reinterpret_cast<float4*>(out + (size_t)(go + 3) * DDIM + dcol) =
                make_float4(lo.x, lo.y, hi.x, hi.y);
        }
    }
}

extern "C" void kernel_launch(void* const* d_in, const int* in_sizes, int n_in,
                              void* d_out, int out_size) {
    const float* x     = (const float*)d_in[0];
    const float* W1    = (const float*)d_in[1];
    const float* b1    = (const float*)d_in[2];
    const float* theta = (const float*)d_in[3];
    const float* W2    = (const float*)d_in[4];
    const float* b2    = (const float*)d_in[5];
    float* out = (float*)d_out;

    int nRows = in_sizes[0] / DDIM;                    // 32768
    int grid  = (nRows + ROWS - 1) / ROWS;             // 256

    size_t smem = (size_t)(DDIM * QDIM + 2 * ROWS * 32 + 2 * QDIM) * sizeof(float);
    static int attr_set = 0;
    if (!attr_set) {
        cudaFuncSetAttribute(ffq_v10, cudaFuncAttributeMaxDynamicSharedMemorySize,
                             (int)smem);
        attr_set = 1;
    }

    ffq_v10<<<grid, NTH, smem>>>(x, W1, b1, theta, W2, b2, out, nRows);
}